// round 9
// baseline (speedup 1.0000x reference)
#include <cuda_runtime.h>
#include <cstdint>
#include <math.h>

typedef unsigned long long u64;

// ---------------- problem constants ----------------
#define T_TOK 512
#define H_DIM 2048
#define N_EXP 32
#define N_GRP 8
#define TOPK_GRP 4
#define TOP_K 6
#define I_DIM 1408
#define I2_DIM 2816
#define NSI 2816
#define NSI2 5632
#define SCALE_F 2.5f
#define MAXM 512
#define NPAIR (T_TOK * TOP_K)   // 3072

// ---------------- scratch (static device memory; no allocation) ----------------
__device__ float g_ACT1[NPAIR * I_DIM];    // routed silu*up
__device__ float g_EO[NPAIR * H_DIM];      // per-pair expert output
__device__ float g_ACTS[T_TOK * NSI];      // shared silu*up
__device__ int   g_topk_ids[NPAIR];
__device__ float g_topk_w[NPAIR];
__device__ int   g_counts[N_EXP];
__device__ int   g_ex_tok[N_EXP * MAXM];
__device__ int   g_ex_pair[N_EXP * MAXM];

// ---------------- helpers ----------------
__device__ __forceinline__ uint32_t smem_u32(const void* p) {
    uint32_t a;
    asm("{ .reg .u64 t; cvta.to.shared.u64 t, %1; cvt.u32.u64 %0, t; }" : "=r"(a) : "l"(p));
    return a;
}
// pack two floats to f16x2 (x0 -> low half, x1 -> high half)
__device__ __forceinline__ uint32_t h2pack(float x0, float x1) {
    uint32_t r;
    asm("cvt.rn.f16x2.f32 %0, %1, %2;" : "=r"(r) : "f"(x1), "f"(x0));
    return r;
}
// residual pack: lo = rn-f16(x - float(hi)) for both halves
__device__ __forceinline__ uint32_t l2pack(float x0, float x1, uint32_t h) {
    float h0, h1;
    asm("{ .reg .f16 a, b; mov.b32 {a, b}, %2; cvt.f32.f16 %0, a; cvt.f32.f16 %1, b; }"
        : "=f"(h0), "=f"(h1) : "r"(h));
    return h2pack(x0 - h0, x1 - h1);
}

#define LDM_X4(r, a) \
    asm volatile("ldmatrix.sync.aligned.m8n8.x4.shared.b16 {%0,%1,%2,%3}, [%4];" \
        : "=r"((r)[0]), "=r"((r)[1]), "=r"((r)[2]), "=r"((r)[3]) : "r"(a))

#define MMA16816(d, a, b0v, b1v) \
    asm volatile("mma.sync.aligned.m16n8k16.row.col.f32.f16.f16.f32 " \
        "{%0,%1,%2,%3}, {%4,%5,%6,%7}, {%8,%9}, {%0,%1,%2,%3};" \
        : "+f"((d)[0]), "+f"((d)[1]), "+f"((d)[2]), "+f"((d)[3]) \
        : "r"((a)[0]), "r"((a)[1]), "r"((a)[2]), "r"((a)[3]), "r"(b0v), "r"(b1v))

#define STS128(addr, v) \
    asm volatile("st.shared.v4.b32 [%0], {%1, %2, %3, %4};" \
        :: "r"(addr), "r"((v).x), "r"((v).y), "r"((v).z), "r"((v).w) : "memory")

#define ROWB 80   // smem row stride (bytes): conflict-free per 8-lane phase

// =====================================================================
// Plain GEMM (down projections): C[rowsC[m]] = A[rowsA[m]] @ (B + e*sB)
// 128x128 tile, BK=32, 8 warps (2x4), 64x32/warp, fp16-split x3 HMMA.
// MMA issue is PRODUCT-MAJOR: 16 independent accs between acc reuse.
// =====================================================================
#define OFF_AH 0
#define OFF_AL 10240
#define OFF_BH 20480
#define OFF_BL 30720
#define BUF_BYTES 40960
#define GEMM_SMEM (2 * BUF_BYTES)   // 80 KB

__global__ void __launch_bounds__(256, 1) wm_gemm_kernel(
    const float* __restrict__ A, const float* __restrict__ B, float* __restrict__ C,
    int Mfixed, const int* __restrict__ Mcnt,
    int nkt, int lda, int ldb, int ldc, size_t strideB,
    const int* __restrict__ rowsA, const int* __restrict__ rowsC)
{
    extern __shared__ char sm_raw[];
    int e = blockIdx.z;
    int M = Mcnt ? Mcnt[e] : Mfixed;
    int m0 = blockIdx.y * 128;
    if (m0 >= M) return;
    int n0 = blockIdx.x * 128;

    uint32_t smem0 = smem_u32(sm_raw);
    int tid = threadIdx.x;
    int wid = tid >> 5, lane = tid & 31;
    int wm = (wid >> 2) * 64, wn = (wid & 3) * 32;

    int prow = tid >> 1;
    int phalf = tid & 1;
    int mg = m0 + prow; if (mg > M - 1) mg = M - 1;
    int arow = rowsA ? rowsA[e * MAXM + mg] : mg;
    const float* Ap = A + (size_t)arow * lda + phalf * 16;
    uint32_t aoff = (uint32_t)(prow * ROWB + phalf * 32);
    int bn = tid & 127;
    int bkh = tid >> 7;
    const float* Bp = B + (size_t)e * strideB + (size_t)(bkh * 16) * ldb + n0 + bn;
    uint32_t boff = (uint32_t)(bn * ROWB + bkh * 32);

    uint32_t a_lm = (uint32_t)((wm + (lane & 15)) * ROWB + (lane >> 4) * 16);
    uint32_t b_lm = (uint32_t)((wn + (lane & 15)) * ROWB + (lane >> 4) * 16);

    float acc[4][4][4];
    #pragma unroll
    for (int i = 0; i < 4; i++)
        #pragma unroll
        for (int j = 0; j < 4; j++)
            #pragma unroll
            for (int q = 0; q < 4; q++) acc[i][j][q] = 0.f;

    float ar[16], br[16];
    #pragma unroll
    for (int j = 0; j < 4; j++) {
        float4 v = *(const float4*)(Ap + 4 * j);
        ar[4*j] = v.x; ar[4*j+1] = v.y; ar[4*j+2] = v.z; ar[4*j+3] = v.w;
    }
    #pragma unroll
    for (int j = 0; j < 16; j++) br[j] = Bp[(size_t)j * ldb];

    {
        uint32_t sb = smem0;
        uint4 h0, h1;
        h0.x = h2pack(ar[0], ar[1]);  h0.y = h2pack(ar[2], ar[3]);
        h0.z = h2pack(ar[4], ar[5]);  h0.w = h2pack(ar[6], ar[7]);
        h1.x = h2pack(ar[8], ar[9]);  h1.y = h2pack(ar[10], ar[11]);
        h1.z = h2pack(ar[12], ar[13]); h1.w = h2pack(ar[14], ar[15]);
        uint4 l0, l1;
        l0.x = l2pack(ar[0], ar[1], h0.x);   l0.y = l2pack(ar[2], ar[3], h0.y);
        l0.z = l2pack(ar[4], ar[5], h0.z);   l0.w = l2pack(ar[6], ar[7], h0.w);
        l1.x = l2pack(ar[8], ar[9], h1.x);   l1.y = l2pack(ar[10], ar[11], h1.y);
        l1.z = l2pack(ar[12], ar[13], h1.z); l1.w = l2pack(ar[14], ar[15], h1.w);
        STS128(sb + OFF_AH + aoff, h0);      STS128(sb + OFF_AH + aoff + 16, h1);
        STS128(sb + OFF_AL + aoff, l0);      STS128(sb + OFF_AL + aoff + 16, l1);
        uint4 g0, g1;
        g0.x = h2pack(br[0], br[1]);  g0.y = h2pack(br[2], br[3]);
        g0.z = h2pack(br[4], br[5]);  g0.w = h2pack(br[6], br[7]);
        g1.x = h2pack(br[8], br[9]);  g1.y = h2pack(br[10], br[11]);
        g1.z = h2pack(br[12], br[13]); g1.w = h2pack(br[14], br[15]);
        uint4 m0v, m1v;
        m0v.x = l2pack(br[0], br[1], g0.x);   m0v.y = l2pack(br[2], br[3], g0.y);
        m0v.z = l2pack(br[4], br[5], g0.z);   m0v.w = l2pack(br[6], br[7], g0.w);
        m1v.x = l2pack(br[8], br[9], g1.x);   m1v.y = l2pack(br[10], br[11], g1.y);
        m1v.z = l2pack(br[12], br[13], g1.z); m1v.w = l2pack(br[14], br[15], g1.w);
        STS128(sb + OFF_BH + boff, g0);       STS128(sb + OFF_BH + boff + 16, g1);
        STS128(sb + OFF_BL + boff, m0v);      STS128(sb + OFF_BL + boff + 16, m1v);
    }
    __syncthreads();

    for (int kt = 0; kt < nkt; kt++) {
        int buf = kt & 1;
        bool more = (kt + 1 < nkt);
        if (more) {
            Ap += 32; Bp += (size_t)32 * ldb;
            #pragma unroll
            for (int j = 0; j < 4; j++) {
                float4 v = *(const float4*)(Ap + 4 * j);
                ar[4*j] = v.x; ar[4*j+1] = v.y; ar[4*j+2] = v.z; ar[4*j+3] = v.w;
            }
            #pragma unroll
            for (int j = 0; j < 16; j++) br[j] = Bp[(size_t)j * ldb];
        }

        uint32_t base = smem0 + buf * BUF_BYTES;
        #pragma unroll
        for (int ks = 0; ks < 2; ks++) {
            uint32_t ah[4][4], al[4][4];
            #pragma unroll
            for (int mf = 0; mf < 4; mf++) {
                uint32_t ad = base + OFF_AH + a_lm + mf * (16 * ROWB) + ks * 32;
                LDM_X4(ah[mf], ad);
                LDM_X4(al[mf], ad + (OFF_AL - OFF_AH));
            }
            uint32_t bh[2][4], bl[2][4];
            #pragma unroll
            for (int nq = 0; nq < 2; nq++) {
                uint32_t bd = base + OFF_BH + b_lm + nq * (16 * ROWB) + ks * 32;
                LDM_X4(bh[nq], bd);
                LDM_X4(bl[nq], bd + (OFF_BL - OFF_BH));
            }
            // product-major: adjacent MMAs always hit different accumulators
            #pragma unroll
            for (int p = 0; p < 3; p++)
                #pragma unroll
                for (int mf = 0; mf < 4; mf++)
                    #pragma unroll
                    for (int nf = 0; nf < 4; nf++) {
                        int nq = nf >> 1, sel = nf & 1;
                        const uint32_t* af = (p == 2) ? al[mf] : ah[mf];
                        uint32_t b0 = (p == 1) ? bl[nq][sel]     : bh[nq][sel];
                        uint32_t b1 = (p == 1) ? bl[nq][sel + 2] : bh[nq][sel + 2];
                        MMA16816(acc[mf][nf], af, b0, b1);
                    }
        }

        if (more) {
            uint32_t sb = smem0 + (buf ^ 1) * BUF_BYTES;
            uint4 h0, h1;
            h0.x = h2pack(ar[0], ar[1]);  h0.y = h2pack(ar[2], ar[3]);
            h0.z = h2pack(ar[4], ar[5]);  h0.w = h2pack(ar[6], ar[7]);
            h1.x = h2pack(ar[8], ar[9]);  h1.y = h2pack(ar[10], ar[11]);
            h1.z = h2pack(ar[12], ar[13]); h1.w = h2pack(ar[14], ar[15]);
            uint4 l0, l1;
            l0.x = l2pack(ar[0], ar[1], h0.x);   l0.y = l2pack(ar[2], ar[3], h0.y);
            l0.z = l2pack(ar[4], ar[5], h0.z);   l0.w = l2pack(ar[6], ar[7], h0.w);
            l1.x = l2pack(ar[8], ar[9], h1.x);   l1.y = l2pack(ar[10], ar[11], h1.y);
            l1.z = l2pack(ar[12], ar[13], h1.z); l1.w = l2pack(ar[14], ar[15], h1.w);
            STS128(sb + OFF_AH + aoff, h0);      STS128(sb + OFF_AH + aoff + 16, h1);
            STS128(sb + OFF_AL + aoff, l0);      STS128(sb + OFF_AL + aoff + 16, l1);
            uint4 g0, g1;
            g0.x = h2pack(br[0], br[1]);  g0.y = h2pack(br[2], br[3]);
            g0.z = h2pack(br[4], br[5]);  g0.w = h2pack(br[6], br[7]);
            g1.x = h2pack(br[8], br[9]);  g1.y = h2pack(br[10], br[11]);
            g1.z = h2pack(br[12], br[13]); g1.w = h2pack(br[14], br[15]);
            uint4 m0v, m1v;
            m0v.x = l2pack(br[0], br[1], g0.x);   m0v.y = l2pack(br[2], br[3], g0.y);
            m0v.z = l2pack(br[4], br[5], g0.z);   m0v.w = l2pack(br[6], br[7], g0.w);
            m1v.x = l2pack(br[8], br[9], g1.x);   m1v.y = l2pack(br[10], br[11], g1.y);
            m1v.z = l2pack(br[12], br[13], g1.z); m1v.w = l2pack(br[14], br[15], g1.w);
            STS128(sb + OFF_BH + boff, g0);       STS128(sb + OFF_BH + boff + 16, g1);
            STS128(sb + OFF_BL + boff, m0v);      STS128(sb + OFF_BL + boff + 16, m1v);
            __syncthreads();
        }
    }

    #pragma unroll
    for (int mf = 0; mf < 4; mf++) {
        int rbase = m0 + wm + mf * 16 + (lane >> 2);
        #pragma unroll
        for (int half = 0; half < 2; half++) {
            int mm = rbase + half * 8;
            if (mm < M) {
                int crow = rowsC ? rowsC[e * MAXM + mm] : mm;
                float* cp = C + (size_t)crow * ldc + n0 + wn + (lane & 3) * 2;
                #pragma unroll
                for (int nf = 0; nf < 4; nf++) {
                    float2 v;
                    v.x = acc[mf][nf][half * 2];
                    v.y = acc[mf][nf][half * 2 + 1];
                    *(float2*)(cp + nf * 8) = v;
                }
            }
        }
    }
}

// =====================================================================
// Fused gate/up GEMM + SiLU epilogue:
//   ACT[rowsC[m], n0+c] = silu(A@B[:, n0+c]) * (A@B[:, halfN+n0+c])
// B-tile = 256 cols (128 gate + 128 paired up). acc[4][2][4][4].
// =====================================================================
#define F_OFF_AH 0
#define F_OFF_AL 10240
#define F_OFF_BH 20480
#define F_OFF_BL 40960
#define F_BUF_BYTES 61440
#define F_GEMM_SMEM (2 * F_BUF_BYTES)   // 120 KB

__global__ void __launch_bounds__(256, 1) fused_gu_kernel(
    const float* __restrict__ A, const float* __restrict__ B, float* __restrict__ ACT,
    int Mfixed, const int* __restrict__ Mcnt,
    int nkt, int lda, int ldb, int halfN, size_t strideB,
    const int* __restrict__ rowsA, const int* __restrict__ rowsC)
{
    extern __shared__ char sm_raw[];
    int e = blockIdx.z;
    int M = Mcnt ? Mcnt[e] : Mfixed;
    int m0 = blockIdx.y * 128;
    if (m0 >= M) return;
    int n0 = blockIdx.x * 128;

    uint32_t smem0 = smem_u32(sm_raw);
    int tid = threadIdx.x;
    int wid = tid >> 5, lane = tid & 31;
    int wm = (wid >> 2) * 64, wn = (wid & 3) * 32;

    // A producer: row = tid>>1, 16 k at (tid&1)*16
    int prow = tid >> 1;
    int phalf = tid & 1;
    int mg = m0 + prow; if (mg > M - 1) mg = M - 1;
    int arow = rowsA ? rowsA[e * MAXM + mg] : mg;
    const float* Ap = A + (size_t)arow * lda + phalf * 16;
    uint32_t aoff = (uint32_t)(prow * ROWB + phalf * 32);
    // B producer: thread = one of 256 columns (gate 0..127, up 128..255), 32 k each
    int bc = tid;
    int bhalf = bc >> 7;
    int gcol = n0 + (bc & 127) + bhalf * halfN;
    const float* Bp = B + (size_t)e * strideB + gcol;
    uint32_t boff = (uint32_t)(bc * ROWB);

    uint32_t a_lm = (uint32_t)((wm + (lane & 15)) * ROWB + (lane >> 4) * 16);
    uint32_t b_lm = (uint32_t)((wn + (lane & 15)) * ROWB + (lane >> 4) * 16);

    float acc[4][2][4][4];
    #pragma unroll
    for (int i = 0; i < 4; i++)
        #pragma unroll
        for (int h = 0; h < 2; h++)
            #pragma unroll
            for (int j = 0; j < 4; j++)
                #pragma unroll
                for (int q = 0; q < 4; q++) acc[i][h][j][q] = 0.f;

    float ar[16], br[32];
    #pragma unroll
    for (int j = 0; j < 4; j++) {
        float4 v = *(const float4*)(Ap + 4 * j);
        ar[4*j] = v.x; ar[4*j+1] = v.y; ar[4*j+2] = v.z; ar[4*j+3] = v.w;
    }
    #pragma unroll
    for (int j = 0; j < 32; j++) br[j] = Bp[(size_t)j * ldb];

    {
        uint32_t sb = smem0;
        uint4 h0, h1;
        h0.x = h2pack(ar[0], ar[1]);  h0.y = h2pack(ar[2], ar[3]);
        h0.z = h2pack(ar[4], ar[5]);  h0.w = h2pack(ar[6], ar[7]);
        h1.x = h2pack(ar[8], ar[9]);  h1.y = h2pack(ar[10], ar[11]);
        h1.z = h2pack(ar[12], ar[13]); h1.w = h2pack(ar[14], ar[15]);
        uint4 l0, l1;
        l0.x = l2pack(ar[0], ar[1], h0.x);   l0.y = l2pack(ar[2], ar[3], h0.y);
        l0.z = l2pack(ar[4], ar[5], h0.z);   l0.w = l2pack(ar[6], ar[7], h0.w);
        l1.x = l2pack(ar[8], ar[9], h1.x);   l1.y = l2pack(ar[10], ar[11], h1.y);
        l1.z = l2pack(ar[12], ar[13], h1.z); l1.w = l2pack(ar[14], ar[15], h1.w);
        STS128(sb + F_OFF_AH + aoff, h0);    STS128(sb + F_OFF_AH + aoff + 16, h1);
        STS128(sb + F_OFF_AL + aoff, l0);    STS128(sb + F_OFF_AL + aoff + 16, l1);
        #pragma unroll
        for (int q = 0; q < 2; q++) {
            uint4 g0, g1, m0v, m1v;
            const float* p = br + 16 * q;
            g0.x = h2pack(p[0], p[1]);   g0.y = h2pack(p[2], p[3]);
            g0.z = h2pack(p[4], p[5]);   g0.w = h2pack(p[6], p[7]);
            g1.x = h2pack(p[8], p[9]);   g1.y = h2pack(p[10], p[11]);
            g1.z = h2pack(p[12], p[13]); g1.w = h2pack(p[14], p[15]);
            m0v.x = l2pack(p[0], p[1], g0.x);    m0v.y = l2pack(p[2], p[3], g0.y);
            m0v.z = l2pack(p[4], p[5], g0.z);    m0v.w = l2pack(p[6], p[7], g0.w);
            m1v.x = l2pack(p[8], p[9], g1.x);    m1v.y = l2pack(p[10], p[11], g1.y);
            m1v.z = l2pack(p[12], p[13], g1.z);  m1v.w = l2pack(p[14], p[15], g1.w);
            STS128(sb + F_OFF_BH + boff + 32*q, g0);
            STS128(sb + F_OFF_BH + boff + 32*q + 16, g1);
            STS128(sb + F_OFF_BL + boff + 32*q, m0v);
            STS128(sb + F_OFF_BL + boff + 32*q + 16, m1v);
        }
    }
    __syncthreads();

    for (int kt = 0; kt < nkt; kt++) {
        int buf = kt & 1;
        bool more = (kt + 1 < nkt);
        if (more) {
            Ap += 32; Bp += (size_t)32 * ldb;
            #pragma unroll
            for (int j = 0; j < 4; j++) {
                float4 v = *(const float4*)(Ap + 4 * j);
                ar[4*j] = v.x; ar[4*j+1] = v.y; ar[4*j+2] = v.z; ar[4*j+3] = v.w;
            }
            #pragma unroll
            for (int j = 0; j < 32; j++) br[j] = Bp[(size_t)j * ldb];
        }

        uint32_t base = smem0 + buf * F_BUF_BYTES;
        #pragma unroll
        for (int ks = 0; ks < 2; ks++) {
            uint32_t ah[4][4], al[4][4];
            #pragma unroll
            for (int mf = 0; mf < 4; mf++) {
                uint32_t ad = base + F_OFF_AH + a_lm + mf * (16 * ROWB) + ks * 32;
                LDM_X4(ah[mf], ad);
                LDM_X4(al[mf], ad + (F_OFF_AL - F_OFF_AH));
            }
            #pragma unroll
            for (int h = 0; h < 2; h++) {
                uint32_t bh[2][4], bl[2][4];
                #pragma unroll
                for (int nq = 0; nq < 2; nq++) {
                    uint32_t bd = base + F_OFF_BH + b_lm + (h * 128 + nq * 16) * ROWB + ks * 32;
                    LDM_X4(bh[nq], bd);
                    LDM_X4(bl[nq], bd + (F_OFF_BL - F_OFF_BH));
                }
                #pragma unroll
                for (int p = 0; p < 3; p++)
                    #pragma unroll
                    for (int mf = 0; mf < 4; mf++)
                        #pragma unroll
                        for (int nf = 0; nf < 4; nf++) {
                            int nq = nf >> 1, sel = nf & 1;
                            const uint32_t* af = (p == 2) ? al[mf] : ah[mf];
                            uint32_t b0 = (p == 1) ? bl[nq][sel]     : bh[nq][sel];
                            uint32_t b1 = (p == 1) ? bl[nq][sel + 2] : bh[nq][sel + 2];
                            MMA16816(acc[mf][h][nf], af, b0, b1);
                        }
            }
        }

        if (more) {
            uint32_t sb = smem0 + (buf ^ 1) * F_BUF_BYTES;
            uint4 h0, h1;
            h0.x = h2pack(ar[0], ar[1]);  h0.y = h2pack(ar[2], ar[3]);
            h0.z = h2pack(ar[4], ar[5]);  h0.w = h2pack(ar[6], ar[7]);
            h1.x = h2pack(ar[8], ar[9]);  h1.y = h2pack(ar[10], ar[11]);
            h1.z = h2pack(ar[12], ar[13]); h1.w = h2pack(ar[14], ar[15]);
            uint4 l0, l1;
            l0.x = l2pack(ar[0], ar[1], h0.x);   l0.y = l2pack(ar[2], ar[3], h0.y);
            l0.z = l2pack(ar[4], ar[5], h0.z);   l0.w = l2pack(ar[6], ar[7], h0.w);
            l1.x = l2pack(ar[8], ar[9], h1.x);   l1.y = l2pack(ar[10], ar[11], h1.y);
            l1.z = l2pack(ar[12], ar[13], h1.z); l1.w = l2pack(ar[14], ar[15], h1.w);
            STS128(sb + F_OFF_AH + aoff, h0);    STS128(sb + F_OFF_AH + aoff + 16, h1);
            STS128(sb + F_OFF_AL + aoff, l0);    STS128(sb + F_OFF_AL + aoff + 16, l1);
            #pragma unroll
            for (int q = 0; q < 2; q++) {
                uint4 g0, g1, m0v, m1v;
                const float* p = br + 16 * q;
                g0.x = h2pack(p[0], p[1]);   g0.y = h2pack(p[2], p[3]);
                g0.z = h2pack(p[4], p[5]);   g0.w = h2pack(p[6], p[7]);
                g1.x = h2pack(p[8], p[9]);   g1.y = h2pack(p[10], p[11]);
                g1.z = h2pack(p[12], p[13]); g1.w = h2pack(p[14], p[15]);
                m0v.x = l2pack(p[0], p[1], g0.x);    m0v.y = l2pack(p[2], p[3], g0.y);
                m0v.z = l2pack(p[4], p[5], g0.z);    m0v.w = l2pack(p[6], p[7], g0.w);
                m1v.x = l2pack(p[8], p[9], g1.x);    m1v.y = l2pack(p[10], p[11], g1.y);
                m1v.z = l2pack(p[12], p[13], g1.z);  m1v.w = l2pack(p[14], p[15], g1.w);
                STS128(sb + F_OFF_BH + boff + 32*q, g0);
                STS128(sb + F_OFF_BH + boff + 32*q + 16, g1);
                STS128(sb + F_OFF_BL + boff + 32*q, m0v);
                STS128(sb + F_OFF_BL + boff + 32*q + 16, m1v);
            }
            __syncthreads();
        }
    }

    // ---- epilogue: act = silu(gate) * up -> ACT rows (gathered) ----
    #pragma unroll
    for (int mf = 0; mf < 4; mf++) {
        int rbase = m0 + wm + mf * 16 + (lane >> 2);
        #pragma unroll
        for (int half = 0; half < 2; half++) {
            int mm = rbase + half * 8;
            if (mm < M) {
                int crow = rowsC ? rowsC[e * MAXM + mm] : mm;
                float* cp = ACT + (size_t)crow * halfN + n0 + wn + (lane & 3) * 2;
                #pragma unroll
                for (int nf = 0; nf < 4; nf++) {
                    float g0v = acc[mf][0][nf][half * 2];
                    float g1v = acc[mf][0][nf][half * 2 + 1];
                    float u0v = acc[mf][1][nf][half * 2];
                    float u1v = acc[mf][1][nf][half * 2 + 1];
                    float2 v;
                    v.x = (g0v / (1.f + expf(-g0v))) * u0v;
                    v.y = (g1v / (1.f + expf(-g1v))) * u1v;
                    *(float2*)(cp + nf * 8) = v;
                }
            }
        }
    }
}

// ---------------- router: logits + sigmoid + grouped topk ----------------
__global__ void __launch_bounds__(256) router_kernel(
    const float* __restrict__ x, const float* __restrict__ gw,
    const float* __restrict__ bias, int* __restrict__ ids, float* __restrict__ tw)
{
    const unsigned FULL = 0xffffffffu;
    int warp = threadIdx.x >> 5, lane = threadIdx.x & 31;
    int t0 = (blockIdx.x * 8 + warp) * 4;
    const float* xr = x + (size_t)t0 * H_DIM;
    float b = bias[lane];

    float acc0 = 0.f, acc1 = 0.f, acc2 = 0.f, acc3 = 0.f;
    #pragma unroll 4
    for (int h = 0; h < H_DIM; h++) {
        float g = gw[h * N_EXP + lane];
        acc0 += xr[h] * g;
        acc1 += xr[H_DIM + h] * g;
        acc2 += xr[2 * H_DIM + h] * g;
        acc3 += xr[3 * H_DIM + h] * g;
    }
    float logits[4] = {acc0, acc1, acc2, acc3};

    for (int tt = 0; tt < 4; tt++) {
        int t = t0 + tt;
        float s   = 1.f / (1.f + expf(-logits[tt]));
        float sfc = s + b;

        float a  = sfc;
        float bb = __shfl_xor_sync(FULL, a, 1);
        float hi = fmaxf(a, bb), lo = fminf(a, bb);
        float hi2 = __shfl_xor_sync(FULL, hi, 2);
        float lo2 = __shfl_xor_sync(FULL, lo, 2);
        float top1   = fmaxf(hi, hi2);
        float second = fmaxf(fminf(hi, hi2), fmaxf(lo, lo2));
        float gscore = top1 + second;
        int gid = lane >> 2;

        int grank = 0;
        #pragma unroll
        for (int j = 0; j < N_GRP; j++) {
            float gj = __shfl_sync(FULL, gscore, j * 4);
            grank += (gj > gscore) || (gj == gscore && j < gid);
        }
        float masked = (grank < TOPK_GRP) ? sfc : -INFINITY;

        int rank = 0;
        #pragma unroll
        for (int j = 0; j < 32; j++) {
            float vj = __shfl_sync(FULL, masked, j);
            rank += (vj > masked) || (vj == masked && j < lane);
        }
        bool sel = rank < TOP_K;

        float wsum = sel ? s : 0.f;
        #pragma unroll
        for (int off = 16; off; off >>= 1) wsum += __shfl_xor_sync(FULL, wsum, off);

        if (sel) {
            ids[t * TOP_K + rank] = lane;
            tw[t * TOP_K + rank]  = s / wsum * SCALE_F;
        }
    }
}

// ---------------- deterministic expert->token compaction ----------------
__global__ void __launch_bounds__(1024) build_lists_kernel(
    const int* __restrict__ ids, int* __restrict__ counts,
    int* __restrict__ ex_tok, int* __restrict__ ex_pair)
{
    const unsigned FULL = 0xffffffffu;
    int e = threadIdx.x >> 5;
    int lane = threadIdx.x & 31;
    int t0 = lane * 16;

    int cnt = 0;
    for (int t = t0; t < t0 + 16; t++)
        #pragma unroll
        for (int k = 0; k < TOP_K; k++)
            if (ids[t * TOP_K + k] == e) cnt++;

    int off = cnt;
    #pragma unroll
    for (int d = 1; d < 32; d <<= 1) {
        int v = __shfl_up_sync(FULL, off, d);
        if (lane >= d) off += v;
    }
    int total = __shfl_sync(FULL, off, 31);
    off -= cnt;

    for (int t = t0; t < t0 + 16; t++)
        #pragma unroll
        for (int k = 0; k < TOP_K; k++)
            if (ids[t * TOP_K + k] == e) {
                ex_tok[e * MAXM + off]  = t;
                ex_pair[e * MAXM + off] = t * TOP_K + k;
                off++;
            }
    if (lane == 0) counts[e] = total;
}

// ---------------- combine: out[t] += sum_k w[t,k] * EO[t*6+k] ----------------
__global__ void __launch_bounds__(256) combine_kernel(
    const float* __restrict__ EO, const float* __restrict__ tw, float* __restrict__ out)
{
    int t = blockIdx.x;
    const float* w = tw + t * TOP_K;
    float w0 = w[0], w1 = w[1], w2v = w[2], w3 = w[3], w4 = w[4], w5 = w[5];
    const float* eb = EO + (size_t)t * TOP_K * H_DIM;
    float* orow = out + (size_t)t * H_DIM;
    for (int c = threadIdx.x; c < H_DIM; c += blockDim.x) {
        float v = orow[c];
        v += w0  * eb[c]
           + w1  * eb[H_DIM + c]
           + w2v * eb[2 * H_DIM + c]
           + w3  * eb[3 * H_DIM + c]
           + w4  * eb[4 * H_DIM + c]
           + w5  * eb[5 * H_DIM + c];
        orow[c] = v;
    }
}

// ---------------- launch ----------------
extern "C" void kernel_launch(void* const* d_in, const int* in_sizes, int n_in,
                              void* d_out, int out_size)
{
    (void)in_sizes; (void)n_in; (void)out_size;
    const float* x      = (const float*)d_in[0];
    const float* gate_w = (const float*)d_in[2];
    const float* cbias  = (const float*)d_in[3];
    const float* w13    = (const float*)d_in[4];
    const float* w2     = (const float*)d_in[5];
    const float* swgu   = (const float*)d_in[6];
    const float* swdn   = (const float*)d_in[7];
    float* out = (float*)d_out;

    float *pACT1, *pEO, *pACTS, *ptw;
    int *pids, *pcnt, *ptok, *ppair;
    cudaGetSymbolAddress((void**)&pACT1, g_ACT1);
    cudaGetSymbolAddress((void**)&pEO,   g_EO);
    cudaGetSymbolAddress((void**)&pACTS, g_ACTS);
    cudaGetSymbolAddress((void**)&ptw,   g_topk_w);
    cudaGetSymbolAddress((void**)&pids,  g_topk_ids);
    cudaGetSymbolAddress((void**)&pcnt,  g_counts);
    cudaGetSymbolAddress((void**)&ptok,  g_ex_tok);
    cudaGetSymbolAddress((void**)&ppair, g_ex_pair);

    cudaFuncSetAttribute(wm_gemm_kernel,
                         cudaFuncAttributeMaxDynamicSharedMemorySize, GEMM_SMEM);
    cudaFuncSetAttribute(fused_gu_kernel,
                         cudaFuncAttributeMaxDynamicSharedMemorySize, F_GEMM_SMEM);

    // 1) router + topk
    router_kernel<<<16, 256>>>(x, gate_w, cbias, pids, ptw);
    // 2) deterministic per-expert lists
    build_lists_kernel<<<1, 1024>>>(pids, pcnt, ptok, ppair);
    // 3) routed gate/up + silu fused: ACT1[pair] = silu_mul(x[tok] @ w13[e])
    fused_gu_kernel<<<dim3(I_DIM / 128, 4, N_EXP), 256, F_GEMM_SMEM>>>(
        x, w13, pACT1, 0, pcnt, H_DIM / 32, H_DIM, I2_DIM, I_DIM,
        (size_t)H_DIM * I2_DIM, ptok, ppair);
    // 4) routed down: EO[pair] = ACT1[pair] @ w2[e]
    wm_gemm_kernel<<<dim3(H_DIM / 128, 4, N_EXP), 256, GEMM_SMEM>>>(
        pACT1, w2, pEO, 0, pcnt, I_DIM / 32, I_DIM, H_DIM, H_DIM,
        (size_t)I_DIM * H_DIM, ppair, ppair);
    // 5) shared gate/up + silu fused: ACTS = silu_mul(x @ shared_w_gu)
    fused_gu_kernel<<<dim3(NSI / 128, 4, 1), 256, F_GEMM_SMEM>>>(
        x, swgu, pACTS, T_TOK, nullptr, H_DIM / 32, H_DIM, NSI2, NSI,
        0, nullptr, nullptr);
    // 6) shared down -> d_out (writes every element)
    wm_gemm_kernel<<<dim3(H_DIM / 128, 4, 1), 256, GEMM_SMEM>>>(
        pACTS, swdn, out, T_TOK, nullptr, NSI / 32, NSI, H_DIM, H_DIM,
        0, nullptr, nullptr);
    // 7) out += weighted routed expert outputs (deterministic order)
    combine_kernel<<<T_TOK, 256>>>(pEO, ptw, out);
}

// round 10
// speedup vs baseline: 1.0812x; 1.0812x over previous
#include <cuda_runtime.h>
#include <cstdint>
#include <math.h>

typedef unsigned long long u64;

// ---------------- problem constants ----------------
#define T_TOK 512
#define H_DIM 2048
#define N_EXP 32
#define N_GRP 8
#define TOPK_GRP 4
#define TOP_K 6
#define I_DIM 1408
#define I2_DIM 2816
#define NSI 2816
#define NSI2 5632
#define SCALE_F 2.5f
#define MAXM 512
#define NPAIR (T_TOK * TOP_K)   // 3072

// ---------------- scratch (static device memory; no allocation) ----------------
__device__ float g_ACT1[NPAIR * I_DIM];    // routed silu*up
__device__ float g_EO[NPAIR * H_DIM];      // per-pair expert output
__device__ float g_ACTS[T_TOK * NSI];      // shared silu*up
__device__ int   g_topk_ids[NPAIR];
__device__ float g_topk_w[NPAIR];
__device__ int   g_counts[N_EXP];
__device__ int   g_ex_tok[N_EXP * MAXM];
__device__ int   g_ex_pair[N_EXP * MAXM];

// ---------------- helpers ----------------
__device__ __forceinline__ uint32_t smem_u32(const void* p) {
    uint32_t a;
    asm("{ .reg .u64 t; cvta.to.shared.u64 t, %1; cvt.u32.u64 %0, t; }" : "=r"(a) : "l"(p));
    return a;
}
__device__ __forceinline__ uint32_t h2pack(float x0, float x1) {
    uint32_t r;
    asm("cvt.rn.f16x2.f32 %0, %1, %2;" : "=r"(r) : "f"(x1), "f"(x0));
    return r;
}
__device__ __forceinline__ uint32_t l2pack(float x0, float x1, uint32_t h) {
    float h0, h1;
    asm("{ .reg .f16 a, b; mov.b32 {a, b}, %2; cvt.f32.f16 %0, a; cvt.f32.f16 %1, b; }"
        : "=f"(h0), "=f"(h1) : "r"(h));
    return h2pack(x0 - h0, x1 - h1);
}

#define LDM_X4(r, a) \
    asm volatile("ldmatrix.sync.aligned.m8n8.x4.shared.b16 {%0,%1,%2,%3}, [%4];" \
        : "=r"((r)[0]), "=r"((r)[1]), "=r"((r)[2]), "=r"((r)[3]) : "r"(a))

#define MMA16816(d, a, b0v, b1v) \
    asm volatile("mma.sync.aligned.m16n8k16.row.col.f32.f16.f16.f32 " \
        "{%0,%1,%2,%3}, {%4,%5,%6,%7}, {%8,%9}, {%0,%1,%2,%3};" \
        : "+f"((d)[0]), "+f"((d)[1]), "+f"((d)[2]), "+f"((d)[3]) \
        : "r"((a)[0]), "r"((a)[1]), "r"((a)[2]), "r"((a)[3]), "r"(b0v), "r"(b1v))

#define STS128(addr, v) \
    asm volatile("st.shared.v4.b32 [%0], {%1, %2, %3, %4};" \
        :: "r"(addr), "r"((v).x), "r"((v).y), "r"((v).z), "r"((v).w) : "memory")

// smem layout (BK=16): row stride 48B, 128 rows per matrix
#define ROWB 48
#define OFF_AH 0
#define OFF_AL 6144
#define OFF_BH 12288
#define OFF_BL 18432
#define BUF_BYTES 24576
#define GEMM_SMEM (2 * BUF_BYTES)   // 48 KB -> 2 CTAs/SM

// convert 8 floats -> hi/lo f16x4 and store (16B each)
__device__ __forceinline__ void cvt_store8(uint32_t sb_h, uint32_t sb_l, const float* f) {
    uint4 h, l;
    h.x = h2pack(f[0], f[1]); h.y = h2pack(f[2], f[3]);
    h.z = h2pack(f[4], f[5]); h.w = h2pack(f[6], f[7]);
    l.x = l2pack(f[0], f[1], h.x); l.y = l2pack(f[2], f[3], h.y);
    l.z = l2pack(f[4], f[5], h.z); l.w = l2pack(f[6], f[7], h.w);
    STS128(sb_h, h);
    STS128(sb_l, l);
}

// =====================================================================
// Plain GEMM (down proj): C[rowsC[m]] = A[rowsA[m]] @ (B + e*strideB)
// CTA 128x128, BK=16, 8 warps (2x4), warp 64x32, fp16-split x3 HMMA.
// =====================================================================
__global__ void __launch_bounds__(256, 2) wm_gemm_kernel(
    const float* __restrict__ A, const float* __restrict__ B, float* __restrict__ C,
    int Mfixed, const int* __restrict__ Mcnt,
    int nkt, int lda, int ldb, int ldc, size_t strideB,
    const int* __restrict__ rowsA, const int* __restrict__ rowsC)
{
    extern __shared__ char sm_raw[];
    int e = blockIdx.z;
    int M = Mcnt ? Mcnt[e] : Mfixed;
    int m0 = blockIdx.y * 128;
    if (m0 >= M) return;
    int n0 = blockIdx.x * 128;

    uint32_t smem0 = smem_u32(sm_raw);
    int tid = threadIdx.x;
    int wid = tid >> 5, lane = tid & 31;
    int wm = (wid >> 2) * 64, wn = (wid & 3) * 32;

    // A producer: row = tid>>1, 8 k at (tid&1)*8
    int prow = tid >> 1;
    int phalf = tid & 1;
    int mg = m0 + prow; if (mg > M - 1) mg = M - 1;
    int arow = rowsA ? rowsA[e * MAXM + mg] : mg;
    const float* Ap = A + (size_t)arow * lda + phalf * 8;
    uint32_t aoff = (uint32_t)(prow * ROWB + phalf * 16);
    // B producer: n = tid&127, 8 k at (tid>>7)*8 (transpose into smem)
    int bn = tid & 127;
    int bkh = tid >> 7;
    const float* Bp = B + (size_t)e * strideB + (size_t)(bkh * 8) * ldb + n0 + bn;
    uint32_t boff = (uint32_t)(bn * ROWB + bkh * 16);

    uint32_t a_lm = (uint32_t)((wm + (lane & 15)) * ROWB + (lane >> 4) * 16);
    uint32_t b_lm = (uint32_t)((wn + (lane & 15)) * ROWB + (lane >> 4) * 16);

    float acc[4][4][4];
    #pragma unroll
    for (int i = 0; i < 4; i++)
        #pragma unroll
        for (int j = 0; j < 4; j++)
            #pragma unroll
            for (int q = 0; q < 4; q++) acc[i][j][q] = 0.f;

    float ar[8], br[8];
    {
        float4 v0 = *(const float4*)Ap;
        float4 v1 = *(const float4*)(Ap + 4);
        ar[0]=v0.x; ar[1]=v0.y; ar[2]=v0.z; ar[3]=v0.w;
        ar[4]=v1.x; ar[5]=v1.y; ar[6]=v1.z; ar[7]=v1.w;
        #pragma unroll
        for (int j = 0; j < 8; j++) br[j] = Bp[(size_t)j * ldb];
        cvt_store8(smem0 + OFF_AH + aoff, smem0 + OFF_AL + aoff, ar);
        cvt_store8(smem0 + OFF_BH + boff, smem0 + OFF_BL + boff, br);
    }
    __syncthreads();

    for (int kt = 0; kt < nkt; kt++) {
        int buf = kt & 1;
        bool more = (kt + 1 < nkt);
        if (more) {
            Ap += 16; Bp += (size_t)16 * ldb;
            float4 v0 = *(const float4*)Ap;
            float4 v1 = *(const float4*)(Ap + 4);
            ar[0]=v0.x; ar[1]=v0.y; ar[2]=v0.z; ar[3]=v0.w;
            ar[4]=v1.x; ar[5]=v1.y; ar[6]=v1.z; ar[7]=v1.w;
            #pragma unroll
            for (int j = 0; j < 8; j++) br[j] = Bp[(size_t)j * ldb];
        }

        uint32_t base = smem0 + buf * BUF_BYTES;
        uint32_t ah[4][4];
        #pragma unroll
        for (int mf = 0; mf < 4; mf++)
            LDM_X4(ah[mf], base + OFF_AH + a_lm + mf * (16 * ROWB));
        uint32_t bh[2][4], bl[2][4];
        #pragma unroll
        for (int nq = 0; nq < 2; nq++) {
            uint32_t bd = base + OFF_BH + b_lm + nq * (16 * ROWB);
            LDM_X4(bh[nq], bd);
            LDM_X4(bl[nq], bd + (OFF_BL - OFF_BH));
        }
        // p0: Ah*Bh ; p1: Ah*Bl  (16 independent accs between reuse)
        #pragma unroll
        for (int mf = 0; mf < 4; mf++)
            #pragma unroll
            for (int nf = 0; nf < 4; nf++) {
                int nq = nf >> 1, sel = nf & 1;
                MMA16816(acc[mf][nf], ah[mf], bh[nq][sel], bh[nq][sel + 2]);
            }
        #pragma unroll
        for (int mf = 0; mf < 4; mf++)
            #pragma unroll
            for (int nf = 0; nf < 4; nf++) {
                int nq = nf >> 1, sel = nf & 1;
                MMA16816(acc[mf][nf], ah[mf], bl[nq][sel], bl[nq][sel + 2]);
            }
        // p2: Al*Bh (load Al late to shorten live ranges)
        uint32_t al[4][4];
        #pragma unroll
        for (int mf = 0; mf < 4; mf++)
            LDM_X4(al[mf], base + OFF_AL + a_lm + mf * (16 * ROWB));
        #pragma unroll
        for (int mf = 0; mf < 4; mf++)
            #pragma unroll
            for (int nf = 0; nf < 4; nf++) {
                int nq = nf >> 1, sel = nf & 1;
                MMA16816(acc[mf][nf], al[mf], bh[nq][sel], bh[nq][sel + 2]);
            }

        if (more) {
            uint32_t sb = smem0 + (buf ^ 1) * BUF_BYTES;
            cvt_store8(sb + OFF_AH + aoff, sb + OFF_AL + aoff, ar);
            cvt_store8(sb + OFF_BH + boff, sb + OFF_BL + boff, br);
        }
        __syncthreads();
    }

    #pragma unroll
    for (int mf = 0; mf < 4; mf++) {
        int rbase = m0 + wm + mf * 16 + (lane >> 2);
        #pragma unroll
        for (int half = 0; half < 2; half++) {
            int mm = rbase + half * 8;
            if (mm < M) {
                int crow = rowsC ? rowsC[e * MAXM + mm] : mm;
                float* cp = C + (size_t)crow * ldc + n0 + wn + (lane & 3) * 2;
                #pragma unroll
                for (int nf = 0; nf < 4; nf++) {
                    float2 v;
                    v.x = acc[mf][nf][half * 2];
                    v.y = acc[mf][nf][half * 2 + 1];
                    *(float2*)(cp + nf * 8) = v;
                }
            }
        }
    }
}

// =====================================================================
// Fused gate/up GEMM + SiLU:
//   ACT[rowsC[m], n0+c] = silu(A@B[:,n0+c]) * (A@B[:,halfN+n0+c])
// CTA 128m x (64 gate + 64 up); warp 64m x 16n per half; acc 64 floats.
// Same smem layout as plain (B cols: 0-63 gate, 64-127 up).
// =====================================================================
__global__ void __launch_bounds__(256, 2) fused_gu_kernel(
    const float* __restrict__ A, const float* __restrict__ B, float* __restrict__ ACT,
    int Mfixed, const int* __restrict__ Mcnt,
    int nkt, int lda, int ldb, int halfN, size_t strideB,
    const int* __restrict__ rowsA, const int* __restrict__ rowsC)
{
    extern __shared__ char sm_raw[];
    int e = blockIdx.z;
    int M = Mcnt ? Mcnt[e] : Mfixed;
    int m0 = blockIdx.y * 128;
    if (m0 >= M) return;
    int n0 = blockIdx.x * 64;

    uint32_t smem0 = smem_u32(sm_raw);
    int tid = threadIdx.x;
    int wid = tid >> 5, lane = tid & 31;
    int wm = (wid >> 2) * 64, wn = (wid & 3) * 16;

    int prow = tid >> 1;
    int phalf = tid & 1;
    int mg = m0 + prow; if (mg > M - 1) mg = M - 1;
    int arow = rowsA ? rowsA[e * MAXM + mg] : mg;
    const float* Ap = A + (size_t)arow * lda + phalf * 8;
    uint32_t aoff = (uint32_t)(prow * ROWB + phalf * 16);
    // B producer: col = tid&127 (0-63 gate, 64-127 up), 8 k at (tid>>7)*8
    int col = tid & 127;
    int bkh = tid >> 7;
    int gcol = n0 + (col & 63) + (col >> 6) * halfN;
    const float* Bp = B + (size_t)e * strideB + (size_t)(bkh * 8) * ldb + gcol;
    uint32_t boff = (uint32_t)(col * ROWB + bkh * 16);

    uint32_t a_lm = (uint32_t)((wm + (lane & 15)) * ROWB + (lane >> 4) * 16);
    uint32_t b_lm0 = (uint32_t)((wn + (lane & 15)) * ROWB + (lane >> 4) * 16);

    float acc[4][2][2][4];
    #pragma unroll
    for (int i = 0; i < 4; i++)
        #pragma unroll
        for (int h = 0; h < 2; h++)
            #pragma unroll
            for (int j = 0; j < 2; j++)
                #pragma unroll
                for (int q = 0; q < 4; q++) acc[i][h][j][q] = 0.f;

    float ar[8], br[8];
    {
        float4 v0 = *(const float4*)Ap;
        float4 v1 = *(const float4*)(Ap + 4);
        ar[0]=v0.x; ar[1]=v0.y; ar[2]=v0.z; ar[3]=v0.w;
        ar[4]=v1.x; ar[5]=v1.y; ar[6]=v1.z; ar[7]=v1.w;
        #pragma unroll
        for (int j = 0; j < 8; j++) br[j] = Bp[(size_t)j * ldb];
        cvt_store8(smem0 + OFF_AH + aoff, smem0 + OFF_AL + aoff, ar);
        cvt_store8(smem0 + OFF_BH + boff, smem0 + OFF_BL + boff, br);
    }
    __syncthreads();

    for (int kt = 0; kt < nkt; kt++) {
        int buf = kt & 1;
        bool more = (kt + 1 < nkt);
        if (more) {
            Ap += 16; Bp += (size_t)16 * ldb;
            float4 v0 = *(const float4*)Ap;
            float4 v1 = *(const float4*)(Ap + 4);
            ar[0]=v0.x; ar[1]=v0.y; ar[2]=v0.z; ar[3]=v0.w;
            ar[4]=v1.x; ar[5]=v1.y; ar[6]=v1.z; ar[7]=v1.w;
            #pragma unroll
            for (int j = 0; j < 8; j++) br[j] = Bp[(size_t)j * ldb];
        }

        uint32_t base = smem0 + buf * BUF_BYTES;
        uint32_t ah[4][4], al[4][4];
        #pragma unroll
        for (int mf = 0; mf < 4; mf++) {
            uint32_t ad = base + OFF_AH + a_lm + mf * (16 * ROWB);
            LDM_X4(ah[mf], ad);
            LDM_X4(al[mf], ad + (OFF_AL - OFF_AH));
        }
        #pragma unroll
        for (int h = 0; h < 2; h++) {
            uint32_t bd = base + OFF_BH + b_lm0 + h * (64 * ROWB);
            uint32_t bh[4], bl[4];
            LDM_X4(bh, bd);
            LDM_X4(bl, bd + (OFF_BL - OFF_BH));
            #pragma unroll
            for (int mf = 0; mf < 4; mf++)
                #pragma unroll
                for (int nf = 0; nf < 2; nf++)
                    MMA16816(acc[mf][h][nf], ah[mf], bh[nf], bh[nf + 2]);
            #pragma unroll
            for (int mf = 0; mf < 4; mf++)
                #pragma unroll
                for (int nf = 0; nf < 2; nf++)
                    MMA16816(acc[mf][h][nf], ah[mf], bl[nf], bl[nf + 2]);
            #pragma unroll
            for (int mf = 0; mf < 4; mf++)
                #pragma unroll
                for (int nf = 0; nf < 2; nf++)
                    MMA16816(acc[mf][h][nf], al[mf], bh[nf], bh[nf + 2]);
        }

        if (more) {
            uint32_t sb = smem0 + (buf ^ 1) * BUF_BYTES;
            cvt_store8(sb + OFF_AH + aoff, sb + OFF_AL + aoff, ar);
            cvt_store8(sb + OFF_BH + boff, sb + OFF_BL + boff, br);
        }
        __syncthreads();
    }

    // epilogue: act = silu(gate) * up -> ACT rows (gathered)
    #pragma unroll
    for (int mf = 0; mf < 4; mf++) {
        int rbase = m0 + wm + mf * 16 + (lane >> 2);
        #pragma unroll
        for (int half = 0; half < 2; half++) {
            int mm = rbase + half * 8;
            if (mm < M) {
                int crow = rowsC ? rowsC[e * MAXM + mm] : mm;
                float* cp = ACT + (size_t)crow * halfN + n0 + wn + (lane & 3) * 2;
                #pragma unroll
                for (int nf = 0; nf < 2; nf++) {
                    float g0v = acc[mf][0][nf][half * 2];
                    float g1v = acc[mf][0][nf][half * 2 + 1];
                    float u0v = acc[mf][1][nf][half * 2];
                    float u1v = acc[mf][1][nf][half * 2 + 1];
                    float2 v;
                    v.x = (g0v / (1.f + expf(-g0v))) * u0v;
                    v.y = (g1v / (1.f + expf(-g1v))) * u1v;
                    *(float2*)(cp + nf * 8) = v;
                }
            }
        }
    }
}

// ---------------- router: logits + sigmoid + grouped topk ----------------
__global__ void __launch_bounds__(256) router_kernel(
    const float* __restrict__ x, const float* __restrict__ gw,
    const float* __restrict__ bias, int* __restrict__ ids, float* __restrict__ tw)
{
    const unsigned FULL = 0xffffffffu;
    int warp = threadIdx.x >> 5, lane = threadIdx.x & 31;
    int t0 = (blockIdx.x * 8 + warp) * 4;
    const float* xr = x + (size_t)t0 * H_DIM;
    float b = bias[lane];

    float acc0 = 0.f, acc1 = 0.f, acc2 = 0.f, acc3 = 0.f;
    #pragma unroll 4
    for (int h = 0; h < H_DIM; h++) {
        float g = gw[h * N_EXP + lane];
        acc0 += xr[h] * g;
        acc1 += xr[H_DIM + h] * g;
        acc2 += xr[2 * H_DIM + h] * g;
        acc3 += xr[3 * H_DIM + h] * g;
    }
    float logits[4] = {acc0, acc1, acc2, acc3};

    for (int tt = 0; tt < 4; tt++) {
        int t = t0 + tt;
        float s   = 1.f / (1.f + expf(-logits[tt]));
        float sfc = s + b;

        float a  = sfc;
        float bb = __shfl_xor_sync(FULL, a, 1);
        float hi = fmaxf(a, bb), lo = fminf(a, bb);
        float hi2 = __shfl_xor_sync(FULL, hi, 2);
        float lo2 = __shfl_xor_sync(FULL, lo, 2);
        float top1   = fmaxf(hi, hi2);
        float second = fmaxf(fminf(hi, hi2), fmaxf(lo, lo2));
        float gscore = top1 + second;
        int gid = lane >> 2;

        int grank = 0;
        #pragma unroll
        for (int j = 0; j < N_GRP; j++) {
            float gj = __shfl_sync(FULL, gscore, j * 4);
            grank += (gj > gscore) || (gj == gscore && j < gid);
        }
        float masked = (grank < TOPK_GRP) ? sfc : -INFINITY;

        int rank = 0;
        #pragma unroll
        for (int j = 0; j < 32; j++) {
            float vj = __shfl_sync(FULL, masked, j);
            rank += (vj > masked) || (vj == masked && j < lane);
        }
        bool sel = rank < TOP_K;

        float wsum = sel ? s : 0.f;
        #pragma unroll
        for (int off = 16; off; off >>= 1) wsum += __shfl_xor_sync(FULL, wsum, off);

        if (sel) {
            ids[t * TOP_K + rank] = lane;
            tw[t * TOP_K + rank]  = s / wsum * SCALE_F;
        }
    }
}

// ---------------- deterministic expert->token compaction ----------------
__global__ void __launch_bounds__(1024) build_lists_kernel(
    const int* __restrict__ ids, int* __restrict__ counts,
    int* __restrict__ ex_tok, int* __restrict__ ex_pair)
{
    const unsigned FULL = 0xffffffffu;
    int e = threadIdx.x >> 5;
    int lane = threadIdx.x & 31;
    int t0 = lane * 16;

    int cnt = 0;
    for (int t = t0; t < t0 + 16; t++)
        #pragma unroll
        for (int k = 0; k < TOP_K; k++)
            if (ids[t * TOP_K + k] == e) cnt++;

    int off = cnt;
    #pragma unroll
    for (int d = 1; d < 32; d <<= 1) {
        int v = __shfl_up_sync(FULL, off, d);
        if (lane >= d) off += v;
    }
    int total = __shfl_sync(FULL, off, 31);
    off -= cnt;

    for (int t = t0; t < t0 + 16; t++)
        #pragma unroll
        for (int k = 0; k < TOP_K; k++)
            if (ids[t * TOP_K + k] == e) {
                ex_tok[e * MAXM + off]  = t;
                ex_pair[e * MAXM + off] = t * TOP_K + k;
                off++;
            }
    if (lane == 0) counts[e] = total;
}

// ---------------- combine: out[t] += sum_k w[t,k] * EO[t*6+k] ----------------
__global__ void __launch_bounds__(256) combine_kernel(
    const float* __restrict__ EO, const float* __restrict__ tw, float* __restrict__ out)
{
    int t = blockIdx.x;
    const float* w = tw + t * TOP_K;
    float w0 = w[0], w1 = w[1], w2v = w[2], w3 = w[3], w4 = w[4], w5 = w[5];
    const float* eb = EO + (size_t)t * TOP_K * H_DIM;
    float* orow = out + (size_t)t * H_DIM;
    for (int c = threadIdx.x; c < H_DIM; c += blockDim.x) {
        float v = orow[c];
        v += w0  * eb[c]
           + w1  * eb[H_DIM + c]
           + w2v * eb[2 * H_DIM + c]
           + w3  * eb[3 * H_DIM + c]
           + w4  * eb[4 * H_DIM + c]
           + w5  * eb[5 * H_DIM + c];
        orow[c] = v;
    }
}

// ---------------- launch ----------------
extern "C" void kernel_launch(void* const* d_in, const int* in_sizes, int n_in,
                              void* d_out, int out_size)
{
    (void)in_sizes; (void)n_in; (void)out_size;
    const float* x      = (const float*)d_in[0];
    const float* gate_w = (const float*)d_in[2];
    const float* cbias  = (const float*)d_in[3];
    const float* w13    = (const float*)d_in[4];
    const float* w2     = (const float*)d_in[5];
    const float* swgu   = (const float*)d_in[6];
    const float* swdn   = (const float*)d_in[7];
    float* out = (float*)d_out;

    float *pACT1, *pEO, *pACTS, *ptw;
    int *pids, *pcnt, *ptok, *ppair;
    cudaGetSymbolAddress((void**)&pACT1, g_ACT1);
    cudaGetSymbolAddress((void**)&pEO,   g_EO);
    cudaGetSymbolAddress((void**)&pACTS, g_ACTS);
    cudaGetSymbolAddress((void**)&ptw,   g_topk_w);
    cudaGetSymbolAddress((void**)&pids,  g_topk_ids);
    cudaGetSymbolAddress((void**)&pcnt,  g_counts);
    cudaGetSymbolAddress((void**)&ptok,  g_ex_tok);
    cudaGetSymbolAddress((void**)&ppair, g_ex_pair);

    cudaFuncSetAttribute(wm_gemm_kernel,
                         cudaFuncAttributeMaxDynamicSharedMemorySize, GEMM_SMEM);
    cudaFuncSetAttribute(fused_gu_kernel,
                         cudaFuncAttributeMaxDynamicSharedMemorySize, GEMM_SMEM);

    // 1) router + topk
    router_kernel<<<16, 256>>>(x, gate_w, cbias, pids, ptw);
    // 2) deterministic per-expert lists
    build_lists_kernel<<<1, 1024>>>(pids, pcnt, ptok, ppair);
    // 3) routed gate/up + silu fused: ACT1[pair] = silu_mul(x[tok] @ w13[e])
    fused_gu_kernel<<<dim3(I_DIM / 64, 4, N_EXP), 256, GEMM_SMEM>>>(
        x, w13, pACT1, 0, pcnt, H_DIM / 16, H_DIM, I2_DIM, I_DIM,
        (size_t)H_DIM * I2_DIM, ptok, ppair);
    // 4) routed down: EO[pair] = ACT1[pair] @ w2[e]
    wm_gemm_kernel<<<dim3(H_DIM / 128, 4, N_EXP), 256, GEMM_SMEM>>>(
        pACT1, w2, pEO, 0, pcnt, I_DIM / 16, I_DIM, H_DIM, H_DIM,
        (size_t)I_DIM * H_DIM, ppair, ppair);
    // 5) shared gate/up + silu fused: ACTS = silu_mul(x @ shared_w_gu)
    fused_gu_kernel<<<dim3(NSI / 64, 4, 1), 256, GEMM_SMEM>>>(
        x, swgu, pACTS, T_TOK, nullptr, H_DIM / 16, H_DIM, NSI2, NSI,
        0, nullptr, nullptr);
    // 6) shared down -> d_out (writes every element)
    wm_gemm_kernel<<<dim3(H_DIM / 128, 4, 1), 256, GEMM_SMEM>>>(
        pACTS, swdn, out, T_TOK, nullptr, NSI / 16, NSI, H_DIM, H_DIM,
        0, nullptr, nullptr);
    // 7) out += weighted routed expert outputs (deterministic order)
    combine_kernel<<<T_TOK, 256>>>(pEO, ptw, out);
}